// round 1
// baseline (speedup 1.0000x reference)
#include <cuda_runtime.h>
#include <math.h>

// Problem constants
#define BB   64
#define TT   512
#define INF  16
#define HH   512
#define JJ   8
#define G3   (3*HH)      // 1536

#define NCTA 128
#define NTH  256
#define JPC  (HH/NCTA)   // 4 hidden units per CTA

// ---------------- device scratch (static globals; no allocation) ------------
__device__ float g_h0t[2][HH][BB];          // layer-0 hidden, transposed [k][b], double buffered
__device__ float g_h1t[2][HH][BB];          // layer-1 hidden
__device__ float g_h1seq[TT][HH][BB];       // all layer-1 states (64 MB)
__device__ float g_act[TT][BB][2*JJ];       // sigmoid(fc) activations (2 MB)
__device__ unsigned g_barcnt;
__device__ unsigned g_bargen;

// ---------------- grid-wide barrier (all NCTA CTAs co-resident) -------------
__device__ __forceinline__ void gridbar()
{
    __syncthreads();
    if (threadIdx.x == 0) {
        __threadfence();                         // release: flush my CTA's stores
        unsigned g = *((volatile unsigned*)&g_bargen);
        if (atomicAdd(&g_barcnt, 1u) == (unsigned)(NCTA - 1)) {
            *((volatile unsigned*)&g_barcnt) = 0u;
            __threadfence();
            *((volatile unsigned*)&g_bargen) = g + 1u;
        } else {
            while (*((volatile unsigned*)&g_bargen) == g) { }
        }
        __threadfence();                         // acquire: CCTL.IVALL -> fresh L1
    }
    __syncthreads();
}

__device__ __forceinline__ float sigf(float x) { return 1.0f / (1.0f + expf(-x)); }

// copy 256x64 floats (one half of an h buffer), global -> smem, float4
__device__ __forceinline__ void stage_tile(float* dst, const float* src)
{
    float4*       d4 = (float4*)dst;
    const float4* s4 = (const float4*)src;
#pragma unroll
    for (int i = 0; i < 16; ++i) {
        int idx = threadIdx.x + i * NTH;         // 4096 float4 total
        d4[idx] = s4[idx];
    }
}

// ---------------- persistent recurrent kernel -------------------------------
// SMEM layout (floats):
//   sWhh0[12][512]  sWih1[12][512]  sWhh1[12][512]   (rows: gate g*4 + local j)
//   sWih0[12][16]
//   sB[48] : [0:12) b_ih0  [12:24) b_hh0  [24:36) b_ih1  [36:48) b_hh1
//   sbuf0[256*64]  sbuf1[256*64]
#define SMEM_FLOATS (3*12*512 + 12*16 + 48 + 2*256*64)
#define SMEM_BYTES  (SMEM_FLOATS * 4)

__global__ void __launch_bounds__(NTH, 1)
rnn_persistent(const float* __restrict__ xg,
               const float* __restrict__ Wih0, const float* __restrict__ Whh0,
               const float* __restrict__ bih0, const float* __restrict__ bhh0,
               const float* __restrict__ Wih1, const float* __restrict__ Whh1,
               const float* __restrict__ bih1, const float* __restrict__ bhh1,
               const float* __restrict__ h0in)
{
    extern __shared__ float smem[];
    float* sWhh0 = smem;
    float* sWih1 = sWhh0 + 12*512;
    float* sWhh1 = sWih1 + 12*512;
    float* sWih0 = sWhh1 + 12*512;
    float* sB    = sWih0 + 12*16;
    float* sbuf0 = sB + 48;
    float* sbuf1 = sbuf0 + 256*64;

    const int c   = blockIdx.x;
    const int tid = threadIdx.x;
    const int jb  = c * JPC;

    // ---- load persistent weight slices into SMEM ----
    for (int idx = tid; idx < 12*512; idx += NTH) {
        int lr = idx >> 9, k = idx & 511;
        int g = lr >> 2, q = lr & 3;
        int grow = g * HH + jb + q;
        sWhh0[idx] = Whh0[grow * HH + k];
        sWih1[idx] = Wih1[grow * HH + k];
        sWhh1[idx] = Whh1[grow * HH + k];
    }
    for (int idx = tid; idx < 12*16; idx += NTH) {
        int lr = idx >> 4, k = idx & 15;
        int g = lr >> 2, q = lr & 3;
        sWih0[idx] = Wih0[(g * HH + jb + q) * INF + k];
    }
    if (tid < 12) {
        int g = tid >> 2, q = tid & 3;
        int grow = g * HH + jb + q;
        sB[tid]      = bih0[grow];
        sB[12 + tid] = bhh0[grow];
        sB[24 + tid] = bih1[grow];
        sB[36 + tid] = bhh1[grow];
    }

    // ---- init transposed hidden state (buffer 0) ----
    for (int idx = tid; idx < JPC * BB; idx += NTH) {
        int q = idx >> 6, b = idx & 63;
        g_h0t[0][jb + q][b] = h0in[(0 * BB + b) * HH + jb + q];
        g_h1t[0][jb + q][b] = h0in[(1 * BB + b) * HH + jb + q];
    }
    gridbar();

    // thread mapping: 8 warps = (2 batch-halves) x (4 local hidden units)
    const int lane = tid & 31;
    const int jl   = (tid >> 5) & 3;
    const int b    = ((tid >> 7) << 5) | lane;
    const int lrow = jb + jl;                    // this thread's hidden unit

    int cur = 0;
    for (int t = 0; t < TT; ++t) {
        const int nxt = cur ^ 1;

        // ================= Phase A : layer-0 GRU ================
        stage_tile(sbuf0, &g_h0t[cur][0][0]);
        stage_tile(sbuf1, &g_h0t[cur][256][0]);
        __syncthreads();

        float ar  = sB[jl]     + sB[12 + jl];
        float az  = sB[4 + jl] + sB[16 + jl];
        float ani = sB[8 + jl];
        float anh = sB[20 + jl];

#pragma unroll 1
        for (int half = 0; half < 2; ++half) {
            const float* hb = half ? sbuf1 : sbuf0;
            const float* pr = sWhh0 + jl * 512       + half * 256;
            const float* pz = sWhh0 + (4 + jl) * 512 + half * 256;
            const float* pn = sWhh0 + (8 + jl) * 512 + half * 256;
#pragma unroll 8
            for (int kk = 0; kk < 256; ++kk) {
                float hv = hb[kk * 64 + b];
                ar  = fmaf(hv, pr[kk], ar);
                az  = fmaf(hv, pz[kk], az);
                anh = fmaf(hv, pn[kk], anh);
            }
        }
        // x @ W_ih0^T  (K = 16)
        {
            const float* xb = xg + ((size_t)b * TT + t) * INF;
#pragma unroll
            for (int k = 0; k < INF; ++k) {
                float xv = __ldg(xb + k);
                ar  = fmaf(xv, sWih0[jl * 16 + k],       ar);
                az  = fmaf(xv, sWih0[(4 + jl) * 16 + k], az);
                ani = fmaf(xv, sWih0[(8 + jl) * 16 + k], ani);
            }
        }
        {
            float hold = (lrow < 256) ? sbuf0[lrow * 64 + b]
                                      : sbuf1[(lrow - 256) * 64 + b];
            float r  = sigf(ar);
            float z  = sigf(az);
            float nn = tanhf(ani + r * anh);
            float hnew = (1.0f - z) * nn + z * hold;
            g_h0t[nxt][lrow][b] = hnew;
        }
        gridbar();

        // ================= Phase B : layer-1 GRU ================
        float air = sB[24 + jl], aiz = sB[28 + jl], ain = sB[32 + jl];
        float ahr = sB[36 + jl], ahz = sB[40 + jl], ahn = sB[44 + jl];

#pragma unroll 1
        for (int half = 0; half < 2; ++half) {
            __syncthreads();
            stage_tile(sbuf0, &g_h0t[nxt][half * 256][0]);   // new layer-0 state
            stage_tile(sbuf1, &g_h1t[cur][half * 256][0]);   // old layer-1 state
            __syncthreads();
            const float* pir = sWih1 + jl * 512       + half * 256;
            const float* piz = sWih1 + (4 + jl) * 512 + half * 256;
            const float* pin = sWih1 + (8 + jl) * 512 + half * 256;
            const float* phr = sWhh1 + jl * 512       + half * 256;
            const float* phz = sWhh1 + (4 + jl) * 512 + half * 256;
            const float* phn = sWhh1 + (8 + jl) * 512 + half * 256;
#pragma unroll 4
            for (int kk = 0; kk < 256; ++kk) {
                float u = sbuf0[kk * 64 + b];
                float v = sbuf1[kk * 64 + b];
                air = fmaf(u, pir[kk], air);
                aiz = fmaf(u, piz[kk], aiz);
                ain = fmaf(u, pin[kk], ain);
                ahr = fmaf(v, phr[kk], ahr);
                ahz = fmaf(v, phz[kk], ahz);
                ahn = fmaf(v, phn[kk], ahn);
            }
        }
        {
            float h1old = g_h1t[cur][lrow][b];
            float r1 = sigf(air + ahr);
            float z1 = sigf(aiz + ahz);
            float n1 = tanhf(ain + r1 * ahn);
            float h1new = (1.0f - z1) * n1 + z1 * h1old;
            g_h1t[nxt][lrow][b] = h1new;
            g_h1seq[t][lrow][b] = h1new;
        }
        gridbar();

        cur = nxt;
    }
}

// ---------------- batch FC head: act = sigmoid(h1 @ fc_W^T + fc_b) ----------
__global__ void __launch_bounds__(NTH)
fc_kernel(const float* __restrict__ fcW, const float* __restrict__ fcb)
{
    __shared__ float sW[16 * 512];
    __shared__ float sb[16];
    const int tid = threadIdx.x;
    for (int idx = tid; idx < 16 * 512; idx += NTH) sW[idx] = fcW[idx];
    if (tid < 16) sb[tid] = fcb[tid];
    __syncthreads();

    const int t  = blockIdx.x;
    const int b  = tid & 63;
    const int og = tid >> 6;            // 4 output groups of 4

    float acc0 = sb[og * 4 + 0], acc1 = sb[og * 4 + 1];
    float acc2 = sb[og * 4 + 2], acc3 = sb[og * 4 + 3];
    const float* w0 = sW + (og * 4 + 0) * 512;
    const float* w1 = sW + (og * 4 + 1) * 512;
    const float* w2 = sW + (og * 4 + 2) * 512;
    const float* w3 = sW + (og * 4 + 3) * 512;
#pragma unroll 8
    for (int k = 0; k < 512; ++k) {
        float hv = g_h1seq[t][k][b];
        acc0 = fmaf(hv, w0[k], acc0);
        acc1 = fmaf(hv, w1[k], acc1);
        acc2 = fmaf(hv, w2[k], acc2);
        acc3 = fmaf(hv, w3[k], acc3);
    }
    g_act[t][b][og * 4 + 0] = sigf(acc0);
    g_act[t][b][og * 4 + 1] = sigf(acc1);
    g_act[t][b][og * 4 + 2] = sigf(acc2);
    g_act[t][b][og * 4 + 3] = sigf(acc3);
}

// ---------------- physics scan (per (b,j) independent, sequential in t) -----
__global__ void __launch_bounds__(BB * JJ)
physics_kernel(const float* __restrict__ theta0,
               const float* __restrict__ omega0,
               float* __restrict__ out)
{
    const int tid = threadIdx.x;         // 512 threads
    const int b = tid >> 3, j = tid & 7;

    float th = theta0[b * JJ + j];
    float om = omega0[b * JJ + j];
    const float ma0 = -0.05f, ma1 = 0.05f;
    const float dt = 1.0f / 60.0f;

#pragma unroll 4
    for (int t = 0; t < TT; ++t) {
        float2 a = *(const float2*)&g_act[t][b][2 * j];
        float Km0 = fmaf(2000.0f, a.x, 100.0f);
        float Km1 = fmaf(2000.0f, a.y, 100.0f);
        float Lm0 = fmaf(0.006f, a.x, 0.06f);
        float Lm1 = fmaf(0.006f, a.y, 0.06f);
        float F0  = Km0 * (Lm0 - ma0 * th);
        float F1  = Km1 * (Lm1 - ma1 * th);
        float tau = ma0 * F0 + ma1 * F1;
        float acc = (tau - 5.0f * th - 0.3f * om) / 0.004f;
        om = fmaf(dt, acc, om);
        th = fmaf(dt, om, th);
        out[((size_t)b * TT + t) * JJ + j] = th;
    }
}

// ---------------- launch ----------------------------------------------------
extern "C" void kernel_launch(void* const* d_in, const int* in_sizes, int n_in,
                              void* d_out, int out_size)
{
    const float* x      = (const float*)d_in[0];
    const float* W_ih0  = (const float*)d_in[1];
    const float* W_hh0  = (const float*)d_in[2];
    const float* b_ih0  = (const float*)d_in[3];
    const float* b_hh0  = (const float*)d_in[4];
    const float* W_ih1  = (const float*)d_in[5];
    const float* W_hh1  = (const float*)d_in[6];
    const float* b_ih1  = (const float*)d_in[7];
    const float* b_hh1  = (const float*)d_in[8];
    const float* fc_W   = (const float*)d_in[9];
    const float* fc_b   = (const float*)d_in[10];
    const float* h0     = (const float*)d_in[11];
    const float* theta0 = (const float*)d_in[12];
    const float* omega0 = (const float*)d_in[13];
    float* out = (float*)d_out;

    cudaFuncSetAttribute(rnn_persistent,
                         cudaFuncAttributeMaxDynamicSharedMemorySize, SMEM_BYTES);

    rnn_persistent<<<NCTA, NTH, SMEM_BYTES>>>(
        x, W_ih0, W_hh0, b_ih0, b_hh0, W_ih1, W_hh1, b_ih1, b_hh1, h0);
    fc_kernel<<<TT, NTH>>>(fc_W, fc_b);
    physics_kernel<<<1, BB * JJ>>>(theta0, omega0, out);
}

// round 2
// speedup vs baseline: 1.4458x; 1.4458x over previous
#include <cuda_runtime.h>
#include <math.h>

// Problem constants
#define BB   64
#define TT   512
#define INF  16
#define HH   512
#define JJ   8

#define NCTA 128
#define NTH  256
#define JPC  (HH/NCTA)   // 4 hidden units per CTA

typedef unsigned long long ull;

// ---------------- device scratch (static globals; no allocation) ------------
__device__ float g_h0t[2][HH][BB];          // layer-0 hidden [k][b], double buffered
__device__ float g_h1t[2][HH][BB];          // layer-1 hidden
__device__ float g_h1seq[TT][HH][BB];       // all layer-1 states (64 MB)
__device__ float g_act[TT][BB][2*JJ];       // sigmoid(fc) activations
__device__ unsigned g_barcnt;
__device__ unsigned g_bargen;

// ---------------- grid-wide barrier (all NCTA CTAs co-resident) -------------
__device__ __forceinline__ void gridbar()
{
    __syncthreads();
    if (threadIdx.x == 0) {
        __threadfence();
        unsigned g = *((volatile unsigned*)&g_bargen);
        if (atomicAdd(&g_barcnt, 1u) == (unsigned)(NCTA - 1)) {
            *((volatile unsigned*)&g_barcnt) = 0u;
            __threadfence();
            *((volatile unsigned*)&g_bargen) = g + 1u;
        } else {
            while (*((volatile unsigned*)&g_bargen) == g) { }
        }
        __threadfence();
    }
    __syncthreads();
}

__device__ __forceinline__ float sigf(float x) { return 1.0f / (1.0f + expf(-x)); }

// ---------------- packed f32x2 helpers --------------------------------------
__device__ __forceinline__ ull dup2(float w)
{ ull d; asm("mov.b64 %0, {%1, %1};" : "=l"(d) : "f"(w)); return d; }

__device__ __forceinline__ ull fma2(ull a, ull b, ull c)
{ ull d; asm("fma.rn.f32x2 %0, %1, %2, %3;" : "=l"(d) : "l"(a), "l"(b), "l"(c)); return d; }

__device__ __forceinline__ float2 unpk(ull v)
{ float2 r; asm("mov.b64 {%0, %1}, %2;" : "=f"(r.x), "=f"(r.y) : "l"(v)); return r; }

// ---------------- persistent recurrent kernel -------------------------------
// SMEM layout (float offsets):
//   [0     ) sWhh0[12*512]      rows r=q*3+g  (q local unit, g in {r,z,n})
//   [6144  ) sWih1[12*512]
//   [12288 ) sWhh1[12*512]
//   [18432 ) sWih0[12*16]
//   [18624 ) sB[48] : bih0[12] bhh0[12] bih1[12] bhh1[12]
//   [18672 ) sH[512*64]  staging (phase A: full h0; phase B: u 256k | v 256k)
//   [51440 ) sR          ull scratch for cross-warp reduction (3072 ull)
#define SMEM_FLOATS (18672 + 32768 + 6144)
#define SMEM_BYTES  (SMEM_FLOATS * 4)

__global__ void __launch_bounds__(NTH, 1)
rnn_persistent(const float* __restrict__ xg,
               const float* __restrict__ Wih0, const float* __restrict__ Whh0,
               const float* __restrict__ bih0, const float* __restrict__ bhh0,
               const float* __restrict__ Wih1, const float* __restrict__ Whh1,
               const float* __restrict__ bih1, const float* __restrict__ bhh1,
               const float* __restrict__ h0in)
{
    extern __shared__ float smem[];
    float* sWhh0 = smem;
    float* sWih1 = smem + 6144;
    float* sWhh1 = smem + 12288;
    float* sWih0 = smem + 18432;
    float* sB    = smem + 18624;
    float* sH    = smem + 18672;            // 32768 floats
    ull*   sR    = (ull*)(smem + 51440);    // 3072 ull

    const int c   = blockIdx.x;
    const int tid = threadIdx.x;
    const int jb  = c * JPC;

    // ---- load persistent weight slices ----
    for (int idx = tid; idx < 12*512; idx += NTH) {
        int r = idx >> 9, k = idx & 511;
        int q = r / 3, g = r - 3*q;
        int grow = g * HH + jb + q;
        sWhh0[idx] = Whh0[grow * HH + k];
        sWih1[idx] = Wih1[grow * HH + k];
        sWhh1[idx] = Whh1[grow * HH + k];
    }
    for (int idx = tid; idx < 12*16; idx += NTH) {
        int r = idx >> 4, k = idx & 15;
        int q = r / 3, g = r - 3*q;
        sWih0[idx] = Wih0[(g * HH + jb + q) * INF + k];
    }
    if (tid < 12) {
        int q = tid / 3, g = tid - 3*q;
        int grow = g * HH + jb + q;
        sB[tid]      = bih0[grow];
        sB[12 + tid] = bhh0[grow];
        sB[24 + tid] = bih1[grow];
        sB[36 + tid] = bhh1[grow];
    }

    // ---- init hidden state (buffer 0) ----
    for (int idx = tid; idx < JPC * BB; idx += NTH) {
        int q = idx >> 6, b = idx & 63;
        g_h0t[0][jb + q][b] = h0in[(0 * BB + b) * HH + jb + q];
        g_h1t[0][jb + q][b] = h0in[(1 * BB + b) * HH + jb + q];
    }
    gridbar();

    const int lane = tid & 31;
    const int warp = tid >> 5;
    const int jh   = warp & 1;       // unit-pair half: units {2jh, 2jh+1}
    const int kc   = warp >> 1;      // k-chunk 0..3
    const int bl   = 2 * lane;       // batch pair base

    int cur = 0;
    for (int t = 0; t < TT; ++t) {
        const int nxt = cur ^ 1;

        // ================= Phase A : layer-0 GRU ================
        // stage full h0[cur] (128 KB) into sH
        {
            float4*       d4 = (float4*)sH;
            const float4* s4 = (const float4*)&g_h0t[cur][0][0];
#pragma unroll
            for (int i = 0; i < 32; ++i)
                d4[tid + i * NTH] = s4[tid + i * NTH];
        }
        __syncthreads();

        {
            ull acc[6];
#pragma unroll
            for (int a = 0; a < 6; ++a) acc[a] = 0ull;

            const float* wbase = sWhh0 + (6 * jh) * 512;
            const int k0 = kc * 128;
#pragma unroll 2
            for (int k4 = 0; k4 < 32; ++k4) {
                const int kk = k0 + 4 * k4;
                ull u0 = *(const ull*)&sH[(kk + 0) * 64 + bl];
                ull u1 = *(const ull*)&sH[(kk + 1) * 64 + bl];
                ull u2 = *(const ull*)&sH[(kk + 2) * 64 + bl];
                ull u3 = *(const ull*)&sH[(kk + 3) * 64 + bl];
#pragma unroll
                for (int a = 0; a < 6; ++a) {
                    float4 w = *(const float4*)&wbase[a * 512 + kk];
                    acc[a] = fma2(dup2(w.x), u0, acc[a]);
                    acc[a] = fma2(dup2(w.y), u1, acc[a]);
                    acc[a] = fma2(dup2(w.z), u2, acc[a]);
                    acc[a] = fma2(dup2(w.w), u3, acc[a]);
                }
            }
#pragma unroll
            for (int a = 0; a < 6; ++a)
                sR[(warp * 6 + a) * 32 + lane] = acc[a];
        }
        __syncthreads();

        // finishers: 128 threads, one (unit, b-pair) each
        if (tid < 128) {
            const int q   = tid >> 5;        // local unit 0..3
            const int fjh = q >> 1, qr = q & 1;
            const int fl  = tid & 31;
            const int fbl = 2 * fl;

            float2 A[3];
#pragma unroll
            for (int g = 0; g < 3; ++g) {
                const int a = qr * 3 + g;
                float sx = 0.f, sy = 0.f;
#pragma unroll
                for (int kk2 = 0; kk2 < 4; ++kk2) {
                    float2 p = unpk(sR[((fjh + 2 * kk2) * 6 + a) * 32 + fl]);
                    sx += p.x; sy += p.y;
                }
                A[g] = make_float2(sx, sy);
            }

            // x @ W_ih0^T part (K = 16) for both batches
            float gi[2][3];
#pragma unroll
            for (int bi = 0; bi < 2; ++bi) {
                const int b = fbl + bi;
                const float4* xb4 = (const float4*)(xg + ((size_t)b * TT + t) * INF);
                float4 x0 = __ldg(xb4 + 0), x1 = __ldg(xb4 + 1);
                float4 x2 = __ldg(xb4 + 2), x3 = __ldg(xb4 + 3);
                float xv[16] = {x0.x,x0.y,x0.z,x0.w, x1.x,x1.y,x1.z,x1.w,
                                x2.x,x2.y,x2.z,x2.w, x3.x,x3.y,x3.z,x3.w};
#pragma unroll
                for (int g = 0; g < 3; ++g) {
                    const float* wr = sWih0 + (q * 3 + g) * 16;
                    float s = 0.f;
#pragma unroll
                    for (int k = 0; k < 16; ++k) s = fmaf(xv[k], wr[k], s);
                    gi[bi][g] = s;
                }
            }

            float2 hold = unpk(*(const ull*)&sH[(jb + q) * 64 + fbl]);
            float hv[2];
#pragma unroll
            for (int bi = 0; bi < 2; ++bi) {
                float Ar = bi ? A[0].y : A[0].x;
                float Az = bi ? A[1].y : A[1].x;
                float An = bi ? A[2].y : A[2].x;
                float ho = bi ? hold.y : hold.x;
                float r  = sigf(sB[q*3+0] + sB[12+q*3+0] + gi[bi][0] + Ar);
                float z  = sigf(sB[q*3+1] + sB[12+q*3+1] + gi[bi][1] + Az);
                float nn = tanhf(sB[q*3+2] + gi[bi][2] + r * (sB[12+q*3+2] + An));
                hv[bi] = (1.0f - z) * nn + z * ho;
            }
            *(float2*)&g_h0t[nxt][jb + q][fbl] = make_float2(hv[0], hv[1]);
        }
        gridbar();

        // ================= Phase B : layer-1 GRU ================
        {
            ull aI[6], aH[6];
#pragma unroll
            for (int a = 0; a < 6; ++a) { aI[a] = 0ull; aH[a] = 0ull; }

            const float* wI = sWih1 + (6 * jh) * 512;
            const float* wH = sWhh1 + (6 * jh) * 512;
            float* sV = sH + 16384;

#pragma unroll 1
            for (int p = 0; p < 2; ++p) {
                // stage u = h0new chunk, v = h1old chunk (64 KB each)
                {
                    float4*       d4 = (float4*)sH;
                    const float4* su = (const float4*)&g_h0t[nxt][p * 256][0];
                    const float4* sv = (const float4*)&g_h1t[cur][p * 256][0];
#pragma unroll
                    for (int i = 0; i < 16; ++i) {
                        d4[tid + i * NTH]        = su[tid + i * NTH];
                        d4[4096 + tid + i * NTH] = sv[tid + i * NTH];
                    }
                }
                __syncthreads();

                const int k0 = kc * 64;
#pragma unroll 2
                for (int k4 = 0; k4 < 16; ++k4) {
                    const int kk = k0 + 4 * k4;       // local staged index
                    const int kw = p * 256 + kk;      // global weight index
                    ull u0 = *(const ull*)&sH[(kk + 0) * 64 + bl];
                    ull u1 = *(const ull*)&sH[(kk + 1) * 64 + bl];
                    ull u2 = *(const ull*)&sH[(kk + 2) * 64 + bl];
                    ull u3 = *(const ull*)&sH[(kk + 3) * 64 + bl];
#pragma unroll
                    for (int a = 0; a < 6; ++a) {
                        float4 w = *(const float4*)&wI[a * 512 + kw];
                        aI[a] = fma2(dup2(w.x), u0, aI[a]);
                        aI[a] = fma2(dup2(w.y), u1, aI[a]);
                        aI[a] = fma2(dup2(w.z), u2, aI[a]);
                        aI[a] = fma2(dup2(w.w), u3, aI[a]);
                    }
                    ull v0 = *(const ull*)&sV[(kk + 0) * 64 + bl];
                    ull v1 = *(const ull*)&sV[(kk + 1) * 64 + bl];
                    ull v2 = *(const ull*)&sV[(kk + 2) * 64 + bl];
                    ull v3 = *(const ull*)&sV[(kk + 3) * 64 + bl];
#pragma unroll
                    for (int a = 0; a < 6; ++a) {
                        float4 w = *(const float4*)&wH[a * 512 + kw];
                        aH[a] = fma2(dup2(w.x), v0, aH[a]);
                        aH[a] = fma2(dup2(w.y), v1, aH[a]);
                        aH[a] = fma2(dup2(w.z), v2, aH[a]);
                        aH[a] = fma2(dup2(w.w), v3, aH[a]);
                    }
                }
                __syncthreads();
            }

#pragma unroll
            for (int a = 0; a < 6; ++a) {
                sR[(warp * 12 + a)     * 32 + lane] = aI[a];
                sR[(warp * 12 + 6 + a) * 32 + lane] = aH[a];
            }
        }
        __syncthreads();

        if (tid < 128) {
            const int q   = tid >> 5;
            const int fjh = q >> 1, qr = q & 1;
            const int fl  = tid & 31;
            const int fbl = 2 * fl;

            float2 I[3], Hh[3];
#pragma unroll
            for (int g = 0; g < 3; ++g) {
                const int a = qr * 3 + g;
                float ix = 0.f, iy = 0.f, hx = 0.f, hy = 0.f;
#pragma unroll
                for (int kk2 = 0; kk2 < 4; ++kk2) {
                    const int w = fjh + 2 * kk2;
                    float2 pi = unpk(sR[(w * 12 + a)     * 32 + fl]);
                    float2 ph = unpk(sR[(w * 12 + 6 + a) * 32 + fl]);
                    ix += pi.x; iy += pi.y; hx += ph.x; hy += ph.y;
                }
                I[g]  = make_float2(ix, iy);
                Hh[g] = make_float2(hx, hy);
            }

            float2 hold = unpk(*(const ull*)&g_h1t[cur][jb + q][fbl]);
            float hv[2];
#pragma unroll
            for (int bi = 0; bi < 2; ++bi) {
                float Ir = bi ? I[0].y : I[0].x;
                float Iz = bi ? I[1].y : I[1].x;
                float In = bi ? I[2].y : I[2].x;
                float Hr = bi ? Hh[0].y : Hh[0].x;
                float Hz = bi ? Hh[1].y : Hh[1].x;
                float Hn = bi ? Hh[2].y : Hh[2].x;
                float ho = bi ? hold.y : hold.x;
                float r1 = sigf(sB[24+q*3+0] + sB[36+q*3+0] + Ir + Hr);
                float z1 = sigf(sB[24+q*3+1] + sB[36+q*3+1] + Iz + Hz);
                float n1 = tanhf(sB[24+q*3+2] + In + r1 * (sB[36+q*3+2] + Hn));
                hv[bi] = (1.0f - z1) * n1 + z1 * ho;
            }
            float2 o = make_float2(hv[0], hv[1]);
            *(float2*)&g_h1t[nxt][jb + q][fbl] = o;
            *(float2*)&g_h1seq[t][jb + q][fbl] = o;
        }
        gridbar();

        cur = nxt;
    }
}

// ---------------- batch FC head: act = sigmoid(h1 @ fc_W^T + fc_b) ----------
__global__ void __launch_bounds__(NTH)
fc_kernel(const float* __restrict__ fcW, const float* __restrict__ fcb)
{
    __shared__ float sW[16 * 512];
    __shared__ float sb[16];
    const int tid = threadIdx.x;
    for (int idx = tid; idx < 16 * 512; idx += NTH) sW[idx] = fcW[idx];
    if (tid < 16) sb[tid] = fcb[tid];
    __syncthreads();

    const int t  = blockIdx.x;
    const int b  = tid & 63;
    const int og = tid >> 6;

    float acc0 = sb[og * 4 + 0], acc1 = sb[og * 4 + 1];
    float acc2 = sb[og * 4 + 2], acc3 = sb[og * 4 + 3];
    const float* w0 = sW + (og * 4 + 0) * 512;
    const float* w1 = sW + (og * 4 + 1) * 512;
    const float* w2 = sW + (og * 4 + 2) * 512;
    const float* w3 = sW + (og * 4 + 3) * 512;
#pragma unroll 8
    for (int k = 0; k < 512; ++k) {
        float hv = g_h1seq[t][k][b];
        acc0 = fmaf(hv, w0[k], acc0);
        acc1 = fmaf(hv, w1[k], acc1);
        acc2 = fmaf(hv, w2[k], acc2);
        acc3 = fmaf(hv, w3[k], acc3);
    }
    g_act[t][b][og * 4 + 0] = sigf(acc0);
    g_act[t][b][og * 4 + 1] = sigf(acc1);
    g_act[t][b][og * 4 + 2] = sigf(acc2);
    g_act[t][b][og * 4 + 3] = sigf(acc3);
}

// ---------------- physics scan ----------------------------------------------
__global__ void __launch_bounds__(BB * JJ)
physics_kernel(const float* __restrict__ theta0,
               const float* __restrict__ omega0,
               float* __restrict__ out)
{
    const int tid = threadIdx.x;
    const int b = tid >> 3, j = tid & 7;

    float th = theta0[b * JJ + j];
    float om = omega0[b * JJ + j];
    const float ma0 = -0.05f, ma1 = 0.05f;
    const float dt = 1.0f / 60.0f;

#pragma unroll 4
    for (int t = 0; t < TT; ++t) {
        float2 a = *(const float2*)&g_act[t][b][2 * j];
        float Km0 = fmaf(2000.0f, a.x, 100.0f);
        float Km1 = fmaf(2000.0f, a.y, 100.0f);
        float Lm0 = fmaf(0.006f, a.x, 0.06f);
        float Lm1 = fmaf(0.006f, a.y, 0.06f);
        float F0  = Km0 * (Lm0 - ma0 * th);
        float F1  = Km1 * (Lm1 - ma1 * th);
        float tau = ma0 * F0 + ma1 * F1;
        float acc = (tau - 5.0f * th - 0.3f * om) / 0.004f;
        om = fmaf(dt, acc, om);
        th = fmaf(dt, om, th);
        out[((size_t)b * TT + t) * JJ + j] = th;
    }
}

// ---------------- launch ----------------------------------------------------
extern "C" void kernel_launch(void* const* d_in, const int* in_sizes, int n_in,
                              void* d_out, int out_size)
{
    const float* x      = (const float*)d_in[0];
    const float* W_ih0  = (const float*)d_in[1];
    const float* W_hh0  = (const float*)d_in[2];
    const float* b_ih0  = (const float*)d_in[3];
    const float* b_hh0  = (const float*)d_in[4];
    const float* W_ih1  = (const float*)d_in[5];
    const float* W_hh1  = (const float*)d_in[6];
    const float* b_ih1  = (const float*)d_in[7];
    const float* b_hh1  = (const float*)d_in[8];
    const float* fc_W   = (const float*)d_in[9];
    const float* fc_b   = (const float*)d_in[10];
    const float* h0     = (const float*)d_in[11];
    const float* theta0 = (const float*)d_in[12];
    const float* omega0 = (const float*)d_in[13];
    float* out = (float*)d_out;

    cudaFuncSetAttribute(rnn_persistent,
                         cudaFuncAttributeMaxDynamicSharedMemorySize, SMEM_BYTES);

    rnn_persistent<<<NCTA, NTH, SMEM_BYTES>>>(
        x, W_ih0, W_hh0, b_ih0, b_hh0, W_ih1, W_hh1, b_ih1, b_hh1, h0);
    fc_kernel<<<TT, NTH>>>(fc_W, fc_b);
    physics_kernel<<<1, BB * JJ>>>(theta0, omega0, out);
}

// round 3
// speedup vs baseline: 1.4484x; 1.0018x over previous
#include <cuda_runtime.h>
#include <math.h>

// Problem constants
#define BB   64
#define TT   512
#define INF  16
#define HH   512
#define JJ   8

#define NCTA 128
#define NTH  256
#define JPC  (HH/NCTA)   // 4 hidden units per CTA

typedef unsigned long long ull;

// ---------------- device scratch (static globals; no allocation) ------------
__device__ float g_h0t[2][HH][BB];          // layer-0 hidden [k][b], double buffered
__device__ float g_h1t[2][HH][BB];          // layer-1 hidden
__device__ float g_h1seq[TT][HH][BB];       // all layer-1 states (64 MB)
__device__ float g_act[TT][BB][2*JJ];       // sigmoid(fc) activations
__device__ unsigned g_barcnt;
__device__ unsigned g_bargen;

// ---------------- grid-wide barrier (all NCTA CTAs co-resident) -------------
__device__ __forceinline__ void gridbar()
{
    __syncthreads();
    if (threadIdx.x == 0) {
        __threadfence();
        unsigned g = *((volatile unsigned*)&g_bargen);
        if (atomicAdd(&g_barcnt, 1u) == (unsigned)(NCTA - 1)) {
            *((volatile unsigned*)&g_barcnt) = 0u;
            __threadfence();
            *((volatile unsigned*)&g_bargen) = g + 1u;
        } else {
            while (*((volatile unsigned*)&g_bargen) == g) { }
        }
        __threadfence();
    }
    __syncthreads();
}

__device__ __forceinline__ float sigf(float x) { return 1.0f / (1.0f + expf(-x)); }

// ---------------- packed f32x2 helpers --------------------------------------
__device__ __forceinline__ ull dup2(float w)
{ ull d; asm("mov.b64 %0, {%1, %1};" : "=l"(d) : "f"(w)); return d; }

__device__ __forceinline__ ull fma2(ull a, ull b, ull c)
{ ull d; asm("fma.rn.f32x2 %0, %1, %2, %3;" : "=l"(d) : "l"(a), "l"(b), "l"(c)); return d; }

__device__ __forceinline__ float2 unpk(ull v)
{ float2 r; asm("mov.b64 {%0, %1}, %2;" : "=f"(r.x), "=f"(r.y) : "l"(v)); return r; }

// ---------------- persistent recurrent kernel -------------------------------
// SMEM layout (float offsets):
//   [0     ) sWhh0[12*512]      rows r=q*3+g  (q local unit, g in {r,z,n})
//   [6144  ) sWih1[12*512]
//   [12288 ) sWhh1[12*512]
//   [18432 ) sWih0[12*16]
//   [18624 ) sB[48] : bih0[12] bhh0[12] bih1[12] bhh1[12]
//   [18672 ) sH[512*64]  staging (phase A: full h0; phase B: u 256k | v 256k)
//   [51440 ) sR          ull scratch for cross-warp reduction (3072 ull)
#define SMEM_FLOATS (18672 + 32768 + 6144)
#define SMEM_BYTES  (SMEM_FLOATS * 4)

__global__ void __launch_bounds__(NTH, 1)
rnn_persistent(const float* __restrict__ xg,
               const float* __restrict__ Wih0, const float* __restrict__ Whh0,
               const float* __restrict__ bih0, const float* __restrict__ bhh0,
               const float* __restrict__ Wih1, const float* __restrict__ Whh1,
               const float* __restrict__ bih1, const float* __restrict__ bhh1,
               const float* __restrict__ h0in)
{
    extern __shared__ float smem[];
    float* sWhh0 = smem;
    float* sWih1 = smem + 6144;
    float* sWhh1 = smem + 12288;
    float* sWih0 = smem + 18432;
    float* sB    = smem + 18624;
    float* sH    = smem + 18672;            // 32768 floats
    ull*   sR    = (ull*)(smem + 51440);    // 3072 ull

    const int c   = blockIdx.x;
    const int tid = threadIdx.x;
    const int jb  = c * JPC;

    // ---- load persistent weight slices ----
    for (int idx = tid; idx < 12*512; idx += NTH) {
        int r = idx >> 9, k = idx & 511;
        int q = r / 3, g = r - 3*q;
        int grow = g * HH + jb + q;
        sWhh0[idx] = Whh0[grow * HH + k];
        sWih1[idx] = Wih1[grow * HH + k];
        sWhh1[idx] = Whh1[grow * HH + k];
    }
    for (int idx = tid; idx < 12*16; idx += NTH) {
        int r = idx >> 4, k = idx & 15;
        int q = r / 3, g = r - 3*q;
        sWih0[idx] = Wih0[(g * HH + jb + q) * INF + k];
    }
    if (tid < 12) {
        int q = tid / 3, g = tid - 3*q;
        int grow = g * HH + jb + q;
        sB[tid]      = bih0[grow];
        sB[12 + tid] = bhh0[grow];
        sB[24 + tid] = bih1[grow];
        sB[36 + tid] = bhh1[grow];
    }

    // ---- init hidden state (buffer 0) ----
    for (int idx = tid; idx < JPC * BB; idx += NTH) {
        int q = idx >> 6, b = idx & 63;
        g_h0t[0][jb + q][b] = h0in[(0 * BB + b) * HH + jb + q];
        g_h1t[0][jb + q][b] = h0in[(1 * BB + b) * HH + jb + q];
    }
    gridbar();

    const int lane = tid & 31;
    const int warp = tid >> 5;
    const int jh   = warp & 1;       // unit-pair half: units {2jh, 2jh+1}
    const int kc   = warp >> 1;      // k-chunk 0..3
    const int bl   = 2 * lane;       // batch pair base

    int cur = 0;
    for (int t = 0; t < TT; ++t) {
        const int nxt = cur ^ 1;

        // ================= Phase A : layer-0 GRU ================
        // stage full h0[cur] (128 KB) into sH
        {
            float4*       d4 = (float4*)sH;
            const float4* s4 = (const float4*)&g_h0t[cur][0][0];
#pragma unroll
            for (int i = 0; i < 32; ++i)
                d4[tid + i * NTH] = s4[tid + i * NTH];
        }
        __syncthreads();

        {
            ull acc[6];
#pragma unroll
            for (int a = 0; a < 6; ++a) acc[a] = 0ull;

            const float* wbase = sWhh0 + (6 * jh) * 512;
            const int k0 = kc * 128;
#pragma unroll 2
            for (int k4 = 0; k4 < 32; ++k4) {
                const int kk = k0 + 4 * k4;
                ull u0 = *(const ull*)&sH[(kk + 0) * 64 + bl];
                ull u1 = *(const ull*)&sH[(kk + 1) * 64 + bl];
                ull u2 = *(const ull*)&sH[(kk + 2) * 64 + bl];
                ull u3 = *(const ull*)&sH[(kk + 3) * 64 + bl];
#pragma unroll
                for (int a = 0; a < 6; ++a) {
                    float4 w = *(const float4*)&wbase[a * 512 + kk];
                    acc[a] = fma2(dup2(w.x), u0, acc[a]);
                    acc[a] = fma2(dup2(w.y), u1, acc[a]);
                    acc[a] = fma2(dup2(w.z), u2, acc[a]);
                    acc[a] = fma2(dup2(w.w), u3, acc[a]);
                }
            }
#pragma unroll
            for (int a = 0; a < 6; ++a)
                sR[(warp * 6 + a) * 32 + lane] = acc[a];
        }
        __syncthreads();

        // finishers: 128 threads, one (unit, b-pair) each
        if (tid < 128) {
            const int q   = tid >> 5;        // local unit 0..3
            const int fjh = q >> 1, qr = q & 1;
            const int fl  = tid & 31;
            const int fbl = 2 * fl;

            float2 A[3];
#pragma unroll
            for (int g = 0; g < 3; ++g) {
                const int a = qr * 3 + g;
                float sx = 0.f, sy = 0.f;
#pragma unroll
                for (int kk2 = 0; kk2 < 4; ++kk2) {
                    float2 p = unpk(sR[((fjh + 2 * kk2) * 6 + a) * 32 + fl]);
                    sx += p.x; sy += p.y;
                }
                A[g] = make_float2(sx, sy);
            }

            // x @ W_ih0^T part (K = 16) for both batches
            float gi[2][3];
#pragma unroll
            for (int bi = 0; bi < 2; ++bi) {
                const int b = fbl + bi;
                const float4* xb4 = (const float4*)(xg + ((size_t)b * TT + t) * INF);
                float4 x0 = __ldg(xb4 + 0), x1 = __ldg(xb4 + 1);
                float4 x2 = __ldg(xb4 + 2), x3 = __ldg(xb4 + 3);
                float xv[16] = {x0.x,x0.y,x0.z,x0.w, x1.x,x1.y,x1.z,x1.w,
                                x2.x,x2.y,x2.z,x2.w, x3.x,x3.y,x3.z,x3.w};
#pragma unroll
                for (int g = 0; g < 3; ++g) {
                    const float* wr = sWih0 + (q * 3 + g) * 16;
                    float s = 0.f;
#pragma unroll
                    for (int k = 0; k < 16; ++k) s = fmaf(xv[k], wr[k], s);
                    gi[bi][g] = s;
                }
            }

            float2 hold = unpk(*(const ull*)&sH[(jb + q) * 64 + fbl]);
            float hv[2];
#pragma unroll
            for (int bi = 0; bi < 2; ++bi) {
                float Ar = bi ? A[0].y : A[0].x;
                float Az = bi ? A[1].y : A[1].x;
                float An = bi ? A[2].y : A[2].x;
                float ho = bi ? hold.y : hold.x;
                float r  = sigf(sB[q*3+0] + sB[12+q*3+0] + gi[bi][0] + Ar);
                float z  = sigf(sB[q*3+1] + sB[12+q*3+1] + gi[bi][1] + Az);
                float nn = tanhf(sB[q*3+2] + gi[bi][2] + r * (sB[12+q*3+2] + An));
                hv[bi] = (1.0f - z) * nn + z * ho;
            }
            *(float2*)&g_h0t[nxt][jb + q][fbl] = make_float2(hv[0], hv[1]);
        }
        gridbar();

        // ================= Phase B : layer-1 GRU ================
        {
            ull aI[6], aH[6];
#pragma unroll
            for (int a = 0; a < 6; ++a) { aI[a] = 0ull; aH[a] = 0ull; }

            const float* wI = sWih1 + (6 * jh) * 512;
            const float* wH = sWhh1 + (6 * jh) * 512;
            float* sV = sH + 16384;

#pragma unroll 1
            for (int p = 0; p < 2; ++p) {
                // stage u = h0new chunk, v = h1old chunk (64 KB each)
                {
                    float4*       d4 = (float4*)sH;
                    const float4* su = (const float4*)&g_h0t[nxt][p * 256][0];
                    const float4* sv = (const float4*)&g_h1t[cur][p * 256][0];
#pragma unroll
                    for (int i = 0; i < 16; ++i) {
                        d4[tid + i * NTH]        = su[tid + i * NTH];
                        d4[4096 + tid + i * NTH] = sv[tid + i * NTH];
                    }
                }
                __syncthreads();

                const int k0 = kc * 64;
#pragma unroll 2
                for (int k4 = 0; k4 < 16; ++k4) {
                    const int kk = k0 + 4 * k4;       // local staged index
                    const int kw = p * 256 + kk;      // global weight index
                    ull u0 = *(const ull*)&sH[(kk + 0) * 64 + bl];
                    ull u1 = *(const ull*)&sH[(kk + 1) * 64 + bl];
                    ull u2 = *(const ull*)&sH[(kk + 2) * 64 + bl];
                    ull u3 = *(const ull*)&sH[(kk + 3) * 64 + bl];
#pragma unroll
                    for (int a = 0; a < 6; ++a) {
                        float4 w = *(const float4*)&wI[a * 512 + kw];
                        aI[a] = fma2(dup2(w.x), u0, aI[a]);
                        aI[a] = fma2(dup2(w.y), u1, aI[a]);
                        aI[a] = fma2(dup2(w.z), u2, aI[a]);
                        aI[a] = fma2(dup2(w.w), u3, aI[a]);
                    }
                    ull v0 = *(const ull*)&sV[(kk + 0) * 64 + bl];
                    ull v1 = *(const ull*)&sV[(kk + 1) * 64 + bl];
                    ull v2 = *(const ull*)&sV[(kk + 2) * 64 + bl];
                    ull v3 = *(const ull*)&sV[(kk + 3) * 64 + bl];
#pragma unroll
                    for (int a = 0; a < 6; ++a) {
                        float4 w = *(const float4*)&wH[a * 512 + kw];
                        aH[a] = fma2(dup2(w.x), v0, aH[a]);
                        aH[a] = fma2(dup2(w.y), v1, aH[a]);
                        aH[a] = fma2(dup2(w.z), v2, aH[a]);
                        aH[a] = fma2(dup2(w.w), v3, aH[a]);
                    }
                }
                __syncthreads();
            }

#pragma unroll
            for (int a = 0; a < 6; ++a) {
                sR[(warp * 12 + a)     * 32 + lane] = aI[a];
                sR[(warp * 12 + 6 + a) * 32 + lane] = aH[a];
            }
        }
        __syncthreads();

        if (tid < 128) {
            const int q   = tid >> 5;
            const int fjh = q >> 1, qr = q & 1;
            const int fl  = tid & 31;
            const int fbl = 2 * fl;

            float2 I[3], Hh[3];
#pragma unroll
            for (int g = 0; g < 3; ++g) {
                const int a = qr * 3 + g;
                float ix = 0.f, iy = 0.f, hx = 0.f, hy = 0.f;
#pragma unroll
                for (int kk2 = 0; kk2 < 4; ++kk2) {
                    const int w = fjh + 2 * kk2;
                    float2 pi = unpk(sR[(w * 12 + a)     * 32 + fl]);
                    float2 ph = unpk(sR[(w * 12 + 6 + a) * 32 + fl]);
                    ix += pi.x; iy += pi.y; hx += ph.x; hy += ph.y;
                }
                I[g]  = make_float2(ix, iy);
                Hh[g] = make_float2(hx, hy);
            }

            float2 hold = unpk(*(const ull*)&g_h1t[cur][jb + q][fbl]);
            float hv[2];
#pragma unroll
            for (int bi = 0; bi < 2; ++bi) {
                float Ir = bi ? I[0].y : I[0].x;
                float Iz = bi ? I[1].y : I[1].x;
                float In = bi ? I[2].y : I[2].x;
                float Hr = bi ? Hh[0].y : Hh[0].x;
                float Hz = bi ? Hh[1].y : Hh[1].x;
                float Hn = bi ? Hh[2].y : Hh[2].x;
                float ho = bi ? hold.y : hold.x;
                float r1 = sigf(sB[24+q*3+0] + sB[36+q*3+0] + Ir + Hr);
                float z1 = sigf(sB[24+q*3+1] + sB[36+q*3+1] + Iz + Hz);
                float n1 = tanhf(sB[24+q*3+2] + In + r1 * (sB[36+q*3+2] + Hn));
                hv[bi] = (1.0f - z1) * n1 + z1 * ho;
            }
            float2 o = make_float2(hv[0], hv[1]);
            *(float2*)&g_h1t[nxt][jb + q][fbl] = o;
            *(float2*)&g_h1seq[t][jb + q][fbl] = o;
        }
        gridbar();

        cur = nxt;
    }
}

// ---------------- batch FC head: act = sigmoid(h1 @ fc_W^T + fc_b) ----------
__global__ void __launch_bounds__(NTH)
fc_kernel(const float* __restrict__ fcW, const float* __restrict__ fcb)
{
    __shared__ float sW[16 * 512];
    __shared__ float sb[16];
    const int tid = threadIdx.x;
    for (int idx = tid; idx < 16 * 512; idx += NTH) sW[idx] = fcW[idx];
    if (tid < 16) sb[tid] = fcb[tid];
    __syncthreads();

    const int t  = blockIdx.x;
    const int b  = tid & 63;
    const int og = tid >> 6;

    float acc0 = sb[og * 4 + 0], acc1 = sb[og * 4 + 1];
    float acc2 = sb[og * 4 + 2], acc3 = sb[og * 4 + 3];
    const float* w0 = sW + (og * 4 + 0) * 512;
    const float* w1 = sW + (og * 4 + 1) * 512;
    const float* w2 = sW + (og * 4 + 2) * 512;
    const float* w3 = sW + (og * 4 + 3) * 512;
#pragma unroll 8
    for (int k = 0; k < 512; ++k) {
        float hv = g_h1seq[t][k][b];
        acc0 = fmaf(hv, w0[k], acc0);
        acc1 = fmaf(hv, w1[k], acc1);
        acc2 = fmaf(hv, w2[k], acc2);
        acc3 = fmaf(hv, w3[k], acc3);
    }
    g_act[t][b][og * 4 + 0] = sigf(acc0);
    g_act[t][b][og * 4 + 1] = sigf(acc1);
    g_act[t][b][og * 4 + 2] = sigf(acc2);
    g_act[t][b][og * 4 + 3] = sigf(acc3);
}

// ---------------- physics scan ----------------------------------------------
__global__ void __launch_bounds__(BB * JJ)
physics_kernel(const float* __restrict__ theta0,
               const float* __restrict__ omega0,
               float* __restrict__ out)
{
    const int tid = threadIdx.x;
    const int b = tid >> 3, j = tid & 7;

    float th = theta0[b * JJ + j];
    float om = omega0[b * JJ + j];
    const float ma0 = -0.05f, ma1 = 0.05f;
    const float dt = 1.0f / 60.0f;

#pragma unroll 4
    for (int t = 0; t < TT; ++t) {
        float2 a = *(const float2*)&g_act[t][b][2 * j];
        float Km0 = fmaf(2000.0f, a.x, 100.0f);
        float Km1 = fmaf(2000.0f, a.y, 100.0f);
        float Lm0 = fmaf(0.006f, a.x, 0.06f);
        float Lm1 = fmaf(0.006f, a.y, 0.06f);
        float F0  = Km0 * (Lm0 - ma0 * th);
        float F1  = Km1 * (Lm1 - ma1 * th);
        float tau = ma0 * F0 + ma1 * F1;
        float acc = (tau - 5.0f * th - 0.3f * om) / 0.004f;
        om = fmaf(dt, acc, om);
        th = fmaf(dt, om, th);
        out[((size_t)b * TT + t) * JJ + j] = th;
    }
}

// ---------------- launch ----------------------------------------------------
extern "C" void kernel_launch(void* const* d_in, const int* in_sizes, int n_in,
                              void* d_out, int out_size)
{
    const float* x      = (const float*)d_in[0];
    const float* W_ih0  = (const float*)d_in[1];
    const float* W_hh0  = (const float*)d_in[2];
    const float* b_ih0  = (const float*)d_in[3];
    const float* b_hh0  = (const float*)d_in[4];
    const float* W_ih1  = (const float*)d_in[5];
    const float* W_hh1  = (const float*)d_in[6];
    const float* b_ih1  = (const float*)d_in[7];
    const float* b_hh1  = (const float*)d_in[8];
    const float* fc_W   = (const float*)d_in[9];
    const float* fc_b   = (const float*)d_in[10];
    const float* h0     = (const float*)d_in[11];
    const float* theta0 = (const float*)d_in[12];
    const float* omega0 = (const float*)d_in[13];
    float* out = (float*)d_out;

    cudaFuncSetAttribute(rnn_persistent,
                         cudaFuncAttributeMaxDynamicSharedMemorySize, SMEM_BYTES);

    rnn_persistent<<<NCTA, NTH, SMEM_BYTES>>>(
        x, W_ih0, W_hh0, b_ih0, b_hh0, W_ih1, W_hh1, b_ih1, b_hh1, h0);
    fc_kernel<<<TT, NTH>>>(fc_W, fc_b);
    physics_kernel<<<1, BB * JJ>>>(theta0, omega0, out);
}

// round 5
// speedup vs baseline: 1.9139x; 1.3214x over previous
#include <cuda_runtime.h>
#include <math.h>
#include <stdint.h>

#define BB 64
#define TT 512
#define INF 16
#define HH 512
#define JJ 8
#define NCTA 128
#define NTH 384
#define JPC 4

typedef unsigned long long ull;

// ---------------- device scratch ------------------------------------------
__device__ float g_h0t[2][HH][BB];
__device__ float g_h1t[2][HH][BB];
__device__ float g_h1seq[TT][HH][BB];      // 64 MB
__device__ float g_act[TT][BB][2*JJ];
__device__ unsigned g_barcnt, g_bargen;

// ---------------- grid barrier --------------------------------------------
__device__ __forceinline__ void gridbar()
{
    __syncthreads();
    if (threadIdx.x == 0) {
        __threadfence();
        unsigned g = *((volatile unsigned*)&g_bargen);
        if (atomicAdd(&g_barcnt, 1u) == NCTA - 1) {
            *((volatile unsigned*)&g_barcnt) = 0u;
            __threadfence();
            *((volatile unsigned*)&g_bargen) = g + 1u;
        } else {
            while (*((volatile unsigned*)&g_bargen) == g) {}
        }
        __threadfence();
    }
    __syncthreads();
}

__device__ __forceinline__ float sigf(float x) { return 1.f / (1.f + expf(-x)); }

__device__ __forceinline__ ull dup2(float w)
{ ull d; asm("mov.b64 %0,{%1,%1};" : "=l"(d) : "f"(w)); return d; }
__device__ __forceinline__ ull fma2(ull a, ull b, ull c)
{ ull d; asm("fma.rn.f32x2 %0,%1,%2,%3;" : "=l"(d) : "l"(a), "l"(b), "l"(c)); return d; }
__device__ __forceinline__ float2 unpk(ull v)
{ float2 r; asm("mov.b64 {%0,%1},%2;" : "=f"(r.x), "=f"(r.y) : "l"(v)); return r; }

__device__ __forceinline__ void cpa16(uint32_t d, const void* s)
{ asm volatile("cp.async.cg.shared.global [%0],[%1],16;" :: "r"(d), "l"(s)); }
__device__ __forceinline__ void cpcommit() { asm volatile("cp.async.commit_group;"); }
template<int N> __device__ __forceinline__ void cpwait()
{ asm volatile("cp.async.wait_group %0;" :: "n"(N)); }
__device__ __forceinline__ uint32_t s2u(const void* p)
{ uint32_t a; asm("{.reg .u64 t; cvta.to.shared.u64 t,%1; cvt.u32.u64 %0,t;}" : "=r"(a) : "l"(p)); return a; }

__device__ __forceinline__ float gru_out(float gr, float gz, float gn,
                                         float hr, float hz, float hn, float ho)
{
    float r = sigf(gr + hr);
    float z = sigf(gz + hz);
    float n = tanhf(gn + r * hn);
    return (1.f - z) * n + z * ho;
}

// ---------------- SMEM layout (float offsets) ------------------------------
// sW[36*512]  rows: 0-11 Whh0, 12-23 Wih1, 24-35 Whh1  (within each: r=q*3+g)
// sWih0[12*16]
// sB[48]: bhh0[12] bih1[12] bhh1[12] bih0[12]
// sU[2][128][64]  sV[2][128][64]  sRed[36*2*32] ull
#define OFF_WIH0 18432
#define OFF_B    18624
#define OFF_U    18672
#define OFF_V    35056
#define OFF_RED  51440
#define SMEM_FLOATS 56048
#define SMEM_BYTES  (SMEM_FLOATS * 4)

__global__ void __launch_bounds__(NTH, 1)
rnn_persistent(const float* __restrict__ xg,
               const float* __restrict__ Wih0, const float* __restrict__ bih0,
               const float* __restrict__ Whh0, const float* __restrict__ bhh0,
               const float* __restrict__ Wih1, const float* __restrict__ bih1,
               const float* __restrict__ Whh1, const float* __restrict__ bhh1,
               const float* __restrict__ h0in)
{
    extern __shared__ float smem[];
    float* sW    = smem;
    float* sWih0 = smem + OFF_WIH0;
    float* sB    = smem + OFF_B;
    float* sU    = smem + OFF_U;
    float* sV    = smem + OFF_V;
    ull*   sRed  = (ull*)(smem + OFF_RED);

    const int tid = threadIdx.x;
    const int jb  = blockIdx.x * JPC;

    // ---- persistent weights ----
    for (int idx = tid; idx < 36 * 512; idx += NTH) {
        int R = idx >> 9, k = idx & 511;
        int r12 = R % 12, q = r12 / 3, g = r12 - 3 * q;
        int grow = g * HH + jb + q;
        const float* M = (R < 12) ? Whh0 : ((R < 24) ? Wih1 : Whh1);
        sW[idx] = M[grow * HH + k];
    }
    for (int idx = tid; idx < 12 * 16; idx += NTH) {
        int r = idx >> 4, k = idx & 15;
        int q = r / 3, g = r - 3 * q;
        sWih0[idx] = Wih0[(g * HH + jb + q) * INF + k];
    }
    if (tid < 12) {
        int q = tid / 3, g = tid - 3 * q;
        int grow = g * HH + jb + q;
        sB[tid]      = bhh0[grow];
        sB[12 + tid] = bih1[grow];
        sB[24 + tid] = bhh1[grow];
        sB[36 + tid] = bih0[grow];
    }

    // ---- init state ----
    float2 h0reg = make_float2(0.f, 0.f), h1reg = make_float2(0.f, 0.f);
    if (tid < 128) {
        int qq = tid >> 5, bl2 = 2 * (tid & 31);
        h0reg.x = h0in[(0 * BB + bl2)     * HH + jb + qq];
        h0reg.y = h0in[(0 * BB + bl2 + 1) * HH + jb + qq];
        h1reg.x = h0in[(1 * BB + bl2)     * HH + jb + qq];
        h1reg.y = h0in[(1 * BB + bl2 + 1) * HH + jb + qq];
        *(float2*)&g_h0t[0][jb + qq][bl2] = h0reg;
        *(float2*)&g_h1t[0][jb + qq][bl2] = h1reg;
        *(float2*)&g_h1t[1][jb + qq][bl2] = h1reg;   // h1[-1] for tick 1
    }

    const uint32_t uU = s2u(sU), uV = s2u(sV);
    const int lane = tid & 31;
    const int warp = tid >> 5;          // 0..11
    const int rg   = warp >> 1;         // row-group 0..5 (6 rows each)
    const int kh   = warp & 1;          // k-sub-half within a quarter
    const int bl   = 2 * lane;
    const float* wrow  = sW + rg * 6 * 512;
    const float* sHsel = (rg >= 4) ? sV : sU;   // Whh1 rows consume v

    for (int tau = 0; tau <= TT; ++tau) {
        const int par = tau & 1;
        gridbar();

        auto stageq = [&](int q, int buf) {
            const char* su = (const char*)&g_h0t[par][q * 128][0];
            const char* sv = (const char*)&g_h1t[par][q * 128][0];
            uint32_t du = uU + buf * 32768u, dv = uV + buf * 32768u;
            for (int i = tid; i < 2048; i += NTH) {
                cpa16(du + i * 16, su + i * 16);
                cpa16(dv + i * 16, sv + i * 16);
            }
            cpcommit();
        };

        stageq(0, 0);
        stageq(1, 1);

        ull acc[6] = {0, 0, 0, 0, 0, 0};
#pragma unroll 1
        for (int q = 0; q < 4; ++q) {
            if (q < 3) cpwait<1>(); else cpwait<0>();
            __syncthreads();
            const float* hb = sHsel + (q & 1) * 8192 + kh * 4096;
            const float* wb = wrow + q * 128 + kh * 64;
#pragma unroll 4
            for (int k4 = 0; k4 < 16; ++k4) {
                const int kk = 4 * k4;
                ull u0 = *(const ull*)&hb[(kk + 0) * 64 + bl];
                ull u1 = *(const ull*)&hb[(kk + 1) * 64 + bl];
                ull u2 = *(const ull*)&hb[(kk + 2) * 64 + bl];
                ull u3 = *(const ull*)&hb[(kk + 3) * 64 + bl];
#pragma unroll
                for (int i = 0; i < 6; ++i) {
                    float4 w = *(const float4*)&wb[i * 512 + kk];
                    acc[i] = fma2(dup2(w.x), u0, acc[i]);
                    acc[i] = fma2(dup2(w.y), u1, acc[i]);
                    acc[i] = fma2(dup2(w.z), u2, acc[i]);
                    acc[i] = fma2(dup2(w.w), u3, acc[i]);
                }
            }
            __syncthreads();
            if (q < 2) stageq(q + 2, q & 1);
        }

#pragma unroll
        for (int i = 0; i < 6; ++i)
            sRed[((rg * 6 + i) * 2 + kh) * 32 + lane] = acc[i];
        __syncthreads();

        if (tid < 128) {
            const int qq = tid >> 5, ln = tid & 31, bl2 = 2 * ln;
            float2 A0[3], I1[3], H1[3];
#pragma unroll
            for (int g = 0; g < 3; ++g) {
                int R = qq * 3 + g;
                float2 a = unpk(sRed[(R * 2) * 32 + ln]);
                float2 b = unpk(sRed[(R * 2 + 1) * 32 + ln]);
                A0[g] = make_float2(a.x + b.x, a.y + b.y);
                R += 12;
                a = unpk(sRed[(R * 2) * 32 + ln]); b = unpk(sRed[(R * 2 + 1) * 32 + ln]);
                I1[g] = make_float2(a.x + b.x, a.y + b.y);
                R += 12;
                a = unpk(sRed[(R * 2) * 32 + ln]); b = unpk(sRed[(R * 2 + 1) * 32 + ln]);
                H1[g] = make_float2(a.x + b.x, a.y + b.y);
            }
            float b0r = sB[qq*3], b0z = sB[qq*3+1], b0n = sB[qq*3+2];
            float i1r = sB[12+qq*3], i1z = sB[13+qq*3], i1n = sB[14+qq*3];
            float h1r = sB[24+qq*3], h1z = sB[25+qq*3], h1n = sB[26+qq*3];

            if (tau < TT) {
                // input projection gi = bih0 + x[tau] @ Wih0^T for both batches
                float gi[2][3];
#pragma unroll
                for (int bi = 0; bi < 2; ++bi) {
                    const int b = bl2 + bi;
                    const float4* xb4 = (const float4*)(xg + ((size_t)b * TT + tau) * INF);
                    float4 x0 = __ldg(xb4), x1 = __ldg(xb4 + 1);
                    float4 x2 = __ldg(xb4 + 2), x3 = __ldg(xb4 + 3);
                    float xv[16] = {x0.x,x0.y,x0.z,x0.w, x1.x,x1.y,x1.z,x1.w,
                                    x2.x,x2.y,x2.z,x2.w, x3.x,x3.y,x3.z,x3.w};
#pragma unroll
                    for (int g = 0; g < 3; ++g) {
                        const float* wr = sWih0 + (qq * 3 + g) * 16;
                        float s = sB[36 + qq * 3 + g];
#pragma unroll
                        for (int k = 0; k < 16; ++k) s = fmaf(xv[k], wr[k], s);
                        gi[bi][g] = s;
                    }
                }
                float nx = gru_out(gi[0][0], gi[0][1], gi[0][2],
                                   A0[0].x + b0r, A0[1].x + b0z, A0[2].x + b0n, h0reg.x);
                float ny = gru_out(gi[1][0], gi[1][1], gi[1][2],
                                   A0[0].y + b0r, A0[1].y + b0z, A0[2].y + b0n, h0reg.y);
                h0reg = make_float2(nx, ny);
                *(float2*)&g_h0t[par ^ 1][jb + qq][bl2] = h0reg;
            }
            if (tau >= 1) {
                float nx = gru_out(I1[0].x + i1r, I1[1].x + i1z, I1[2].x + i1n,
                                   H1[0].x + h1r, H1[1].x + h1z, H1[2].x + h1n, h1reg.x);
                float ny = gru_out(I1[0].y + i1r, I1[1].y + i1z, I1[2].y + i1n,
                                   H1[0].y + h1r, H1[1].y + h1z, H1[2].y + h1n, h1reg.y);
                h1reg = make_float2(nx, ny);
                *(float2*)&g_h1t[par ^ 1][jb + qq][bl2] = h1reg;
                *(float2*)&g_h1seq[tau - 1][jb + qq][bl2] = h1reg;
            }
        }
    }
}

// ---------------- batch FC head ---------------------------------------------
__global__ void __launch_bounds__(256)
fc_kernel(const float* __restrict__ fcW, const float* __restrict__ fcb)
{
    __shared__ float sW[16 * 512];
    __shared__ float sb[16];
    const int tid = threadIdx.x;
    for (int idx = tid; idx < 16 * 512; idx += 256) sW[idx] = fcW[idx];
    if (tid < 16) sb[tid] = fcb[tid];
    __syncthreads();
    const int t = blockIdx.x, b = tid & 63, og = tid >> 6;
    float a0 = sb[og*4], a1 = sb[og*4+1], a2 = sb[og*4+2], a3 = sb[og*4+3];
    const float* w0 = sW + (og*4)*512;
    const float* w1 = sW + (og*4+1)*512;
    const float* w2 = sW + (og*4+2)*512;
    const float* w3 = sW + (og*4+3)*512;
#pragma unroll 8
    for (int k = 0; k < 512; ++k) {
        float hv = g_h1seq[t][k][b];
        a0 = fmaf(hv, w0[k], a0); a1 = fmaf(hv, w1[k], a1);
        a2 = fmaf(hv, w2[k], a2); a3 = fmaf(hv, w3[k], a3);
    }
    g_act[t][b][og*4]   = sigf(a0);
    g_act[t][b][og*4+1] = sigf(a1);
    g_act[t][b][og*4+2] = sigf(a2);
    g_act[t][b][og*4+3] = sigf(a3);
}

// ---------------- physics scan ----------------------------------------------
__global__ void __launch_bounds__(BB * JJ)
physics_kernel(const float* __restrict__ theta0, const float* __restrict__ omega0,
               float* __restrict__ out)
{
    const int tid = threadIdx.x, b = tid >> 3, j = tid & 7;
    float th = theta0[b * JJ + j], om = omega0[b * JJ + j];
    const float ma0 = -0.05f, ma1 = 0.05f, dt = 1.f / 60.f;
#pragma unroll 4
    for (int t = 0; t < TT; ++t) {
        float2 a = *(const float2*)&g_act[t][b][2 * j];
        float Km0 = fmaf(2000.f, a.x, 100.f), Km1 = fmaf(2000.f, a.y, 100.f);
        float Lm0 = fmaf(0.006f, a.x, 0.06f), Lm1 = fmaf(0.006f, a.y, 0.06f);
        float F0 = Km0 * (Lm0 - ma0 * th), F1 = Km1 * (Lm1 - ma1 * th);
        float tau = ma0 * F0 + ma1 * F1;
        float acc = (tau - 5.f * th - 0.3f * om) / 0.004f;
        om = fmaf(dt, acc, om);
        th = fmaf(dt, om, th);
        out[((size_t)b * TT + t) * JJ + j] = th;
    }
}

// ---------------- launch ----------------------------------------------------
extern "C" void kernel_launch(void* const* d_in, const int* in_sizes, int n_in,
                              void* d_out, int out_size)
{
    const float* x      = (const float*)d_in[0];
    const float* W_ih0  = (const float*)d_in[1];
    const float* W_hh0  = (const float*)d_in[2];
    const float* b_ih0  = (const float*)d_in[3];
    const float* b_hh0  = (const float*)d_in[4];
    const float* W_ih1  = (const float*)d_in[5];
    const float* W_hh1  = (const float*)d_in[6];
    const float* b_ih1  = (const float*)d_in[7];
    const float* b_hh1  = (const float*)d_in[8];
    const float* fc_W   = (const float*)d_in[9];
    const float* fc_b   = (const float*)d_in[10];
    const float* h0     = (const float*)d_in[11];
    const float* theta0 = (const float*)d_in[12];
    const float* omega0 = (const float*)d_in[13];
    float* out = (float*)d_out;

    cudaFuncSetAttribute(rnn_persistent,
                         cudaFuncAttributeMaxDynamicSharedMemorySize, SMEM_BYTES);

    rnn_persistent<<<NCTA, NTH, SMEM_BYTES>>>(
        x, W_ih0, b_ih0, W_hh0, b_hh0, W_ih1, b_ih1, W_hh1, b_hh1, h0);
    fc_kernel<<<TT, 256>>>(fc_W, fc_b);
    physics_kernel<<<1, BB * JJ>>>(theta0, omega0, out);
}